// round 3
// baseline (speedup 1.0000x reference)
#include <cuda_runtime.h>
#include <math.h>

// Problem constants
#define NN   100000
#define EE   3200000
#define INF  512
#define HF   256
#define OUTF 64
#define TOTE (EE + NN)

// ---------------- device scratch (no allocs allowed) ----------------
__device__ float g_bufA[(size_t)NN * HF];   // 102.4 MB
__device__ float g_bufB[(size_t)NN * HF];   // 102.4 MB
__device__ float g_h  [(size_t)NN * OUTF];
__device__ float g_p1 [(size_t)NN * OUTF];
__device__ float g_p2 [(size_t)NN * OUTF];
__device__ float g_dinv[NN];
__device__ int   g_deg[NN];
__device__ int   g_cursor[NN];
__device__ int   g_rowptr[NN + 1];
__device__ int   g_cols[TOTE];
__device__ float g_norm[TOTE];
__device__ float g_stats[2 * HF];

__device__ __forceinline__ float gelu_exact(float x) {
    return 0.5f * x * (1.0f + erff(x * 0.70710678118654752f));
}

// ---------------- graph preprocessing ----------------
__global__ void init_kernel() {
    int i = blockIdx.x * blockDim.x + threadIdx.x;
    if (i < NN) { g_deg[i] = 1; g_cursor[i] = 0; }  // self-loop counted
}

__global__ void degree_kernel(const int* __restrict__ row) {
    int e = blockIdx.x * blockDim.x + threadIdx.x;
    if (e < EE) atomicAdd(&g_deg[row[e]], 1);
}

__global__ void dinv_kernel() {
    int i = blockIdx.x * blockDim.x + threadIdx.x;
    if (i < NN) g_dinv[i] = rsqrtf((float)g_deg[i]);
}

// single-block exclusive scan of g_deg -> g_rowptr (100001 entries)
__global__ void scan_kernel() {
    __shared__ int part[1024];
    int tid = threadIdx.x;
    const int chunk = (NN + 1023) / 1024;
    int start = tid * chunk;
    int end = min(start + chunk, NN);
    int s = 0;
    for (int j = start; j < end; j++) s += g_deg[j];
    part[tid] = s;
    __syncthreads();
    for (int off = 1; off < 1024; off <<= 1) {
        int v = (tid >= off) ? part[tid - off] : 0;
        __syncthreads();
        part[tid] += v;
        __syncthreads();
    }
    int run = part[tid] - s;  // exclusive
    for (int j = start; j < end; j++) { g_rowptr[j] = run; run += g_deg[j]; }
    if (tid == 1023) g_rowptr[NN] = part[1023];
}

// scatter edges (idx < EE) and self-loops (idx >= EE) into CSR
__global__ void scatter_kernel(const int* __restrict__ row,
                               const int* __restrict__ col) {
    int idx = blockIdx.x * blockDim.x + threadIdx.x;
    if (idx >= TOTE) return;
    int r, c;
    if (idx < EE) { r = row[idx]; c = col[idx]; }
    else          { r = idx - EE; c = r; }
    int pos = g_rowptr[r] + atomicAdd(&g_cursor[r], 1);
    g_cols[pos] = c;
    g_norm[pos] = g_dinv[r] * g_dinv[c];
}

// ---------------- GEMM: C[M,Nd] = A[M,K] @ B[K,Nd] + bias ----------------
template <int BM, int BN, int BK, int TM, int TN>
__global__ __launch_bounds__((BM / TM) * (BN / TN))
void gemm_kernel(const float* __restrict__ A, const float* __restrict__ B,
                 const float* __restrict__ bias, float* __restrict__ C,
                 int M, int K, int Nd) {
    constexpr int THREADS = (BM / TM) * (BN / TN);   // 256
    __shared__ float sA[BK][BM + 4];
    __shared__ float sB[BK][BN];
    int tid = threadIdx.x;
    int m0 = blockIdx.y * BM;
    int n0 = blockIdx.x * BN;
    int tx = tid % (BN / TN);   // 0..15
    int ty = tid / (BN / TN);   // 0..15

    float acc[TM][TN];
#pragma unroll
    for (int i = 0; i < TM; i++)
#pragma unroll
        for (int j = 0; j < TN; j++) acc[i][j] = 0.f;

    const int a_row  = tid / (BK / 4);        // 0..63
    const int a_col4 = (tid % (BK / 4)) * 4;  // 0,4,8,12
    const int b_row  = tid / (BN / 4);        // 0..15
    const int b_col4 = (tid % (BN / 4)) * 4;

    for (int k0 = 0; k0 < K; k0 += BK) {
#pragma unroll
        for (int p = 0; p < BM; p += THREADS / (BK / 4)) {  // 2 passes of 64 rows
            int m = m0 + a_row + p;
            float4 v = make_float4(0.f, 0.f, 0.f, 0.f);
            if (m < M) v = *(const float4*)(A + (size_t)m * K + k0 + a_col4);
            sA[a_col4 + 0][a_row + p] = v.x;
            sA[a_col4 + 1][a_row + p] = v.y;
            sA[a_col4 + 2][a_row + p] = v.z;
            sA[a_col4 + 3][a_row + p] = v.w;
        }
        {
            float4 v = *(const float4*)(B + (size_t)(k0 + b_row) * Nd + n0 + b_col4);
            *(float4*)&sB[b_row][b_col4] = v;
        }
        __syncthreads();
#pragma unroll
        for (int kk = 0; kk < BK; kk++) {
            float ra[TM], rb[TN];
#pragma unroll
            for (int i = 0; i < TM; i++) ra[i] = sA[kk][ty * TM + i];
#pragma unroll
            for (int j = 0; j < TN; j++) rb[j] = sB[kk][tx * TN + j];
#pragma unroll
            for (int i = 0; i < TM; i++)
#pragma unroll
                for (int j = 0; j < TN; j++) acc[i][j] += ra[i] * rb[j];
        }
        __syncthreads();
    }
#pragma unroll
    for (int i = 0; i < TM; i++) {
        int m = m0 + ty * TM + i;
        if (m >= M) continue;
#pragma unroll
        for (int j = 0; j < TN; j++) {
            int n = n0 + tx * TN + j;
            C[(size_t)m * Nd + n] = acc[i][j] + bias[n];
        }
    }
}

// ---------------- BatchNorm stats + apply ----------------
__global__ void bn_stats_kernel(const float* __restrict__ pre, int n) {
    int f = threadIdx.x;  // 256 features
    float s = 0.f, sq = 0.f;
    for (int r = blockIdx.x; r < n; r += gridDim.x) {
        float v = pre[(size_t)r * HF + f];
        s += v; sq += v * v;
    }
    atomicAdd(&g_stats[f], s);
    atomicAdd(&g_stats[HF + f], sq);
}

__global__ void bn_apply_kernel(const float* __restrict__ pre, const float* __restrict__ res,
                                const float* __restrict__ gamma, const float* __restrict__ beta,
                                float* __restrict__ outp, int n) {
    size_t i = (size_t)blockIdx.x * blockDim.x + threadIdx.x;  // float4 index
    size_t total4 = (size_t)n * HF / 4;
    if (i >= total4) return;
    int f = (int)((i * 4) % HF);
    float4 p  = ((const float4*)pre)[i];
    float4 sm = *(const float4*)&g_stats[f];
    float4 sq = *(const float4*)&g_stats[HF + f];
    float4 gm = *(const float4*)&gamma[f];
    float4 bt = *(const float4*)&beta[f];
    const float invn = 1.0f / (float)n;
    float4 o;
    {
        float mean = sm.x * invn; float var = sq.x * invn - mean * mean;
        float v = gm.x * (p.x - mean) * rsqrtf(var + 1e-5f) + bt.x;
        if (res) v += ((const float4*)res)[i].x;
        o.x = gelu_exact(v);
    }
    {
        float mean = sm.y * invn; float var = sq.y * invn - mean * mean;
        float v = gm.y * (p.y - mean) * rsqrtf(var + 1e-5f) + bt.y;
        if (res) v += ((const float4*)res)[i].y;
        o.y = gelu_exact(v);
    }
    {
        float mean = sm.z * invn; float var = sq.z * invn - mean * mean;
        float v = gm.z * (p.z - mean) * rsqrtf(var + 1e-5f) + bt.z;
        if (res) v += ((const float4*)res)[i].z;
        o.z = gelu_exact(v);
    }
    {
        float mean = sm.w * invn; float var = sq.w * invn - mean * mean;
        float v = gm.w * (p.w - mean) * rsqrtf(var + 1e-5f) + bt.w;
        if (res) v += ((const float4*)res)[i].w;
        o.w = gelu_exact(v);
    }
    ((float4*)outp)[i] = o;
}

// ---------------- propagation ----------------
__global__ void prop_init_kernel(float* __restrict__ acc, const float* __restrict__ alpha) {
    size_t i = (size_t)blockIdx.x * blockDim.x + threadIdx.x;
    if (i < (size_t)NN * OUTF) acc[i] = (alpha[0] * (1.0f / 1.5f)) * g_h[i];
}

__global__ __launch_bounds__(256)
void prop_kernel(const float* __restrict__ src, float* __restrict__ dst,
                 float* __restrict__ acc, const float* __restrict__ alpha, int k) {
    int r = blockIdx.x * 4 + (threadIdx.x >> 6);
    int t = threadIdx.x & 63;
    if (r >= NN) return;
    int s = g_rowptr[r], e = g_rowptr[r + 1];
    float a = 0.f;
    int i = s;
    for (; i + 4 <= e; i += 4) {
        int   c0 = g_cols[i + 0], c1 = g_cols[i + 1], c2 = g_cols[i + 2], c3 = g_cols[i + 3];
        float w0 = g_norm[i + 0], w1 = g_norm[i + 1], w2 = g_norm[i + 2], w3 = g_norm[i + 3];
        a += w0 * src[c0 * OUTF + t];
        a += w1 * src[c1 * OUTF + t];
        a += w2 * src[c2 * OUTF + t];
        a += w3 * src[c3 * OUTF + t];
    }
    for (; i < e; i++) a += g_norm[i] * src[g_cols[i] * OUTF + t];
    dst[(size_t)r * OUTF + t] = a;
    acc[(size_t)r * OUTF + t] += (alpha[k] * (1.0f / 1.5f)) * a;
}

// ---------------- launch ----------------
extern "C" void kernel_launch(void* const* d_in, const int* in_sizes, int n_in,
                              void* d_out, int out_size) {
    const float* x  = (const float*)d_in[0];
    const int*   ei = (const int*)d_in[1];      // int32! (jax x64 disabled)
    const float *w1 = (const float*)d_in[2],  *b1 = (const float*)d_in[3];
    const float *ga1 = (const float*)d_in[4], *be1 = (const float*)d_in[5];
    const float *w2 = (const float*)d_in[6],  *b2 = (const float*)d_in[7];
    const float *ga2 = (const float*)d_in[8], *be2 = (const float*)d_in[9];
    const float *w3 = (const float*)d_in[10], *b3 = (const float*)d_in[11];
    const float *ga3 = (const float*)d_in[12], *be3 = (const float*)d_in[13];
    const float *w4 = (const float*)d_in[14], *b4 = (const float*)d_in[15];
    const float *alpha = (const float*)d_in[16];
    float* out = (float*)d_out;

    const int* rowp = ei;        // edge_index[0]
    const int* colp = ei + EE;   // edge_index[1]

    float *bufA, *bufB, *hbuf, *p1, *p2, *stats;
    cudaGetSymbolAddress((void**)&bufA, g_bufA);
    cudaGetSymbolAddress((void**)&bufB, g_bufB);
    cudaGetSymbolAddress((void**)&hbuf, g_h);
    cudaGetSymbolAddress((void**)&p1, g_p1);
    cudaGetSymbolAddress((void**)&p2, g_p2);
    cudaGetSymbolAddress((void**)&stats, g_stats);

    // --- graph preprocessing: degrees -> dinv -> CSR ---
    init_kernel<<<(NN + 255) / 256, 256>>>();
    degree_kernel<<<(EE + 255) / 256, 256>>>(rowp);
    dinv_kernel<<<(NN + 255) / 256, 256>>>();
    scan_kernel<<<1, 1024>>>();
    scatter_kernel<<<(TOTE + 255) / 256, 256>>>(rowp, colp);

    const int gy = (NN + 127) / 128;        // 782
    const int elem4 = (int)(((size_t)NN * HF / 4 + 255) / 256);

    // --- layer 1: pre = x@w1+b1 ; x0 = gelu(bn(pre)) -> bufB ---
    gemm_kernel<128, 64, 16, 8, 4><<<dim3(HF / 64, gy), 256>>>(x, w1, b1, bufA, NN, INF, HF);
    cudaMemsetAsync(stats, 0, 2 * HF * sizeof(float));
    bn_stats_kernel<<<1024, 256>>>(bufA, NN);
    bn_apply_kernel<<<elem4, 256>>>(bufA, nullptr, ga1, be1, bufB, NN);

    // --- layer 2: pre = x0@w2+b2 ; x1 = gelu(bn(pre)+x0) -> bufA ---
    gemm_kernel<128, 64, 16, 8, 4><<<dim3(HF / 64, gy), 256>>>(bufB, w2, b2, bufA, NN, HF, HF);
    cudaMemsetAsync(stats, 0, 2 * HF * sizeof(float));
    bn_stats_kernel<<<1024, 256>>>(bufA, NN);
    bn_apply_kernel<<<elem4, 256>>>(bufA, bufB, ga2, be2, bufA, NN);

    // --- layer 3: pre = x1@w3+b3 ; x2 = gelu(bn(pre)+x1) -> bufB ---
    gemm_kernel<128, 64, 16, 8, 4><<<dim3(HF / 64, gy), 256>>>(bufA, w3, b3, bufB, NN, HF, HF);
    cudaMemsetAsync(stats, 0, 2 * HF * sizeof(float));
    bn_stats_kernel<<<1024, 256>>>(bufB, NN);
    bn_apply_kernel<<<elem4, 256>>>(bufB, bufA, ga3, be3, bufB, NN);

    // --- layer 4: h = x2@w4+b4 ---
    gemm_kernel<128, 64, 16, 8, 4><<<dim3(1, gy), 256>>>(bufB, w4, b4, hbuf, NN, HF, OUTF);

    // --- propagation: acc = sum_k (alpha[k]/TEMP) * A_hat^k h ---
    prop_init_kernel<<<(int)(((size_t)NN * OUTF + 255) / 256), 256>>>(out, alpha);
    const float* src = hbuf;
    float* dsts[2] = { p1, p2 };
    for (int k = 1; k <= 10; k++) {
        float* dst = dsts[(k - 1) & 1];
        prop_kernel<<<(NN + 3) / 4, 256>>>(src, dst, out, alpha, k);
        src = dst;
    }
}

// round 7
// speedup vs baseline: 1.2686x; 1.2686x over previous
#include <cuda_runtime.h>
#include <cuda_bf16.h>
#include <math.h>
#include <stdint.h>

// Problem constants
#define NN   100000
#define EE   3200000
#define INF  512
#define HF   256
#define OUTF 64
#define TOTE (EE + NN)

// ---------------- device scratch (no allocs allowed) ----------------
__device__ float g_bufA[(size_t)NN * HF];
__device__ float g_bufB[(size_t)NN * HF];
__device__ float g_h  [(size_t)NN * OUTF];
__device__ float g_p1 [(size_t)NN * OUTF];
__device__ float g_p2 [(size_t)NN * OUTF];
__device__ float g_dinv[NN];
__device__ int   g_deg[NN];
__device__ int   g_cursor[NN];
__device__ int   g_rowptr[NN + 1];
__device__ int   g_cols[TOTE];
__device__ float g_norm[TOTE];
__device__ float g_stats[2 * HF];
__device__ int   g_bsum[512];
__device__ int   g_boff[512];

// bf16 split operand buffers (hi/lo), max shape 100k x 512
__device__ alignas(16) __nv_bfloat16 g_ahi[(size_t)NN * INF];
__device__ alignas(16) __nv_bfloat16 g_alo[(size_t)NN * INF];
// weight operands [Nd, K] (K-major)
__device__ alignas(16) __nv_bfloat16 g_w1hi[HF * INF],  g_w1lo[HF * INF];
__device__ alignas(16) __nv_bfloat16 g_w2hi[HF * HF],   g_w2lo[HF * HF];
__device__ alignas(16) __nv_bfloat16 g_w3hi[HF * HF],   g_w3lo[HF * HF];
__device__ alignas(16) __nv_bfloat16 g_w4hi[OUTF * HF], g_w4lo[OUTF * HF];

__device__ __forceinline__ float gelu_exact(float x) {
    return 0.5f * x * (1.0f + erff(x * 0.70710678118654752f));
}

__device__ __forceinline__ uint32_t smem_u32(const void* p) {
    uint32_t a;
    asm("{ .reg .u64 t; cvta.to.shared.u64 t, %1; cvt.u32.u64 %0, t; }" : "=r"(a) : "l"(p));
    return a;
}

#define LDSM_X4(r0, r1, r2, r3, addr) \
    asm volatile("ldmatrix.sync.aligned.m8n8.x4.shared.b16 {%0,%1,%2,%3}, [%4];" \
        : "=r"(r0), "=r"(r1), "=r"(r2), "=r"(r3) : "r"(addr))

#define MMA_BF16(c, a0, a1, a2, a3, b0, b1) \
    asm volatile("mma.sync.aligned.m16n8k16.row.col.f32.bf16.bf16.f32 " \
        "{%0,%1,%2,%3}, {%4,%5,%6,%7}, {%8,%9}, {%0,%1,%2,%3};" \
        : "+f"((c)[0]), "+f"((c)[1]), "+f"((c)[2]), "+f"((c)[3]) \
        : "r"(a0), "r"(a1), "r"(a2), "r"(a3), "r"(b0), "r"(b1))

// ---------------- graph preprocessing ----------------
__global__ void init_kernel() {
    int i = blockIdx.x * blockDim.x + threadIdx.x;
    if (i < NN) { g_deg[i] = 1; g_cursor[i] = 0; }
}
__global__ void degree_kernel(const int* __restrict__ row) {
    int e = blockIdx.x * blockDim.x + threadIdx.x;
    if (e < EE) atomicAdd(&g_deg[row[e]], 1);
}
__global__ void dinv_kernel() {
    int i = blockIdx.x * blockDim.x + threadIdx.x;
    if (i < NN) g_dinv[i] = rsqrtf((float)g_deg[i]);
}
// 3-phase parallel scan
__global__ void scan1_kernel() {
    __shared__ int sh[256];
    int t = threadIdx.x, i = blockIdx.x * 256 + t;
    int v = (i < NN) ? g_deg[i] : 0;
    sh[t] = v; __syncthreads();
    for (int o = 1; o < 256; o <<= 1) {
        int u = (t >= o) ? sh[t - o] : 0;
        __syncthreads(); sh[t] += u; __syncthreads();
    }
    if (i < NN) g_rowptr[i] = sh[t] - v;
    if (t == 255) g_bsum[blockIdx.x] = sh[255];
}
__global__ void scan2_kernel(int nb) {
    __shared__ int sh[512];
    int t = threadIdx.x;
    int v = (t < nb) ? g_bsum[t] : 0;
    sh[t] = v; __syncthreads();
    for (int o = 1; o < 512; o <<= 1) {
        int u = (t >= o) ? sh[t - o] : 0;
        __syncthreads(); sh[t] += u; __syncthreads();
    }
    g_boff[t] = sh[t] - v;
}
__global__ void scan3_kernel() {
    int i = blockIdx.x * 256 + threadIdx.x;
    if (i < NN) g_rowptr[i] += g_boff[blockIdx.x];
    if (i == 0) g_rowptr[NN] = TOTE;
}
__global__ void scatter_kernel(const int* __restrict__ row, const int* __restrict__ col) {
    int idx = blockIdx.x * blockDim.x + threadIdx.x;
    if (idx >= TOTE) return;
    int r, c;
    if (idx < EE) { r = row[idx]; c = col[idx]; }
    else          { r = idx - EE; c = r; }
    int pos = g_rowptr[r] + atomicAdd(&g_cursor[r], 1);
    g_cols[pos] = c;
    g_norm[pos] = g_dinv[r] * g_dinv[c];
}

// ---------------- fp32 -> bf16 hi/lo splits ----------------
__global__ void split2_kernel(const float* __restrict__ in,
                              __nv_bfloat162* __restrict__ hi,
                              __nv_bfloat162* __restrict__ lo, size_t n2) {
    size_t i = (size_t)blockIdx.x * blockDim.x + threadIdx.x;
    if (i >= n2) return;
    float2 v = ((const float2*)in)[i];
    __nv_bfloat16 hx = __float2bfloat16(v.x), hy = __float2bfloat16(v.y);
    __nv_bfloat16 lx = __float2bfloat16(v.x - __bfloat162float(hx));
    __nv_bfloat16 ly = __float2bfloat16(v.y - __bfloat162float(hy));
    hi[i] = __nv_bfloat162(hx, hy);
    lo[i] = __nv_bfloat162(lx, ly);
}
// W [K,Nd] fp32 -> Whi/Wlo [Nd,K] bf16 (K-major for mma B operand)
__global__ void wsplit_kernel(const float* __restrict__ w,
                              __nv_bfloat16* __restrict__ whi,
                              __nv_bfloat16* __restrict__ wlo, int K, int Nd) {
    int idx = blockIdx.x * blockDim.x + threadIdx.x;
    if (idx >= K * Nd) return;
    int k = idx / Nd, n = idx % Nd;
    float v = w[(size_t)k * Nd + n];
    __nv_bfloat16 h = __float2bfloat16(v);
    whi[(size_t)n * K + k] = h;
    wlo[(size_t)n * K + k] = __float2bfloat16(v - __bfloat162float(h));
}

// ---------------- HMMA split-bf16 GEMM ----------------
// C[M,ND] = A[M,KK] * B[ND,KK]^T + bias. 3-pass: AhBh + AhBl + AlBh.
// Block 128x64 tile, BK=32, 8 warps (4 M x 2 N), warp tile 32x32.
template <int ND, int KK>
__global__ __launch_bounds__(256)
void hmma_gemm_kernel(const __nv_bfloat16* __restrict__ Ahi, const __nv_bfloat16* __restrict__ Alo,
                      const __nv_bfloat16* __restrict__ Bhi, const __nv_bfloat16* __restrict__ Blo,
                      const float* __restrict__ bias, float* __restrict__ C, int M) {
    constexpr int BK = 32;
    constexpr int LDS = BK + 8;   // 40 bf16 stride -> conflict-free ldmatrix
    __shared__ __nv_bfloat16 sAh[128 * LDS], sAl[128 * LDS];
    __shared__ __nv_bfloat16 sBh[64 * LDS],  sBl[64 * LDS];

    const int tid = threadIdx.x, lane = tid & 31, warp = tid >> 5;
    const int wm = warp & 3;      // 0..3 along M
    const int wn = warp >> 2;     // 0..1 along N
    const int m0 = blockIdx.x * 128;
    const int n0 = blockIdx.y * 64;

    float acc[2][4][4];
#pragma unroll
    for (int i = 0; i < 2; i++)
#pragma unroll
        for (int j = 0; j < 4; j++)
#pragma unroll
            for (int q = 0; q < 4; q++) acc[i][j][q] = 0.f;

    const uint32_t bAh = smem_u32(sAh), bAl = smem_u32(sAl);
    const uint32_t bBh = smem_u32(sBh), bBl = smem_u32(sBl);

    // ldmatrix per-thread offsets (elements)
    const int ra = lane & 15;                   // A row within 16-tile
    const int ca = (lane & 16) ? 8 : 0;         // A col half
    const int rb = (lane & 7) + ((lane & 16) ? 8 : 0);  // B row within 16-pair
    const int cb = (lane & 8) ? 8 : 0;          // B col half

    for (int k0 = 0; k0 < KK; k0 += BK) {
        // load A chunk: 128 x 32
#pragma unroll
        for (int it = tid; it < 512; it += 256) {
            int r = it >> 2, q = it & 3;
            int gr = m0 + r;
            uint4 vh = make_uint4(0, 0, 0, 0), vl = make_uint4(0, 0, 0, 0);
            if (gr < M) {
                vh = *(const uint4*)(Ahi + (size_t)gr * KK + k0 + q * 8);
                vl = *(const uint4*)(Alo + (size_t)gr * KK + k0 + q * 8);
            }
            *(uint4*)&sAh[r * LDS + q * 8] = vh;
            *(uint4*)&sAl[r * LDS + q * 8] = vl;
        }
        // load B chunk: 64 x 32
        {
            int r = tid >> 2, q = tid & 3;
            *(uint4*)&sBh[r * LDS + q * 8] = *(const uint4*)(Bhi + (size_t)(n0 + r) * KK + k0 + q * 8);
            *(uint4*)&sBl[r * LDS + q * 8] = *(const uint4*)(Blo + (size_t)(n0 + r) * KK + k0 + q * 8);
        }
        __syncthreads();

#pragma unroll
        for (int ks = 0; ks < 2; ks++) {
            const int kb = ks * 16;
            uint32_t ah[2][4], al[2][4], bh[2][4], bl[2][4];
#pragma unroll
            for (int mt = 0; mt < 2; mt++) {
                uint32_t off = (uint32_t)(((wm * 32 + mt * 16 + ra) * LDS + kb + ca) * 2);
                LDSM_X4(ah[mt][0], ah[mt][1], ah[mt][2], ah[mt][3], bAh + off);
                LDSM_X4(al[mt][0], al[mt][1], al[mt][2], al[mt][3], bAl + off);
            }
#pragma unroll
            for (int np = 0; np < 2; np++) {
                uint32_t off = (uint32_t)(((wn * 32 + np * 16 + rb) * LDS + kb + cb) * 2);
                LDSM_X4(bh[np][0], bh[np][1], bh[np][2], bh[np][3], bBh + off);
                LDSM_X4(bl[np][0], bl[np][1], bl[np][2], bl[np][3], bBl + off);
            }
#pragma unroll
            for (int mt = 0; mt < 2; mt++)
#pragma unroll
                for (int nt = 0; nt < 4; nt++) {
                    int np = nt >> 1, h = (nt & 1) * 2;
                    MMA_BF16(acc[mt][nt], ah[mt][0], ah[mt][1], ah[mt][2], ah[mt][3],
                             bh[np][h], bh[np][h + 1]);
                    MMA_BF16(acc[mt][nt], ah[mt][0], ah[mt][1], ah[mt][2], ah[mt][3],
                             bl[np][h], bl[np][h + 1]);
                    MMA_BF16(acc[mt][nt], al[mt][0], al[mt][1], al[mt][2], al[mt][3],
                             bh[np][h], bh[np][h + 1]);
                }
        }
        __syncthreads();
    }

    // epilogue
#pragma unroll
    for (int mt = 0; mt < 2; mt++) {
        int row = m0 + wm * 32 + mt * 16 + (lane >> 2);
#pragma unroll
        for (int nt = 0; nt < 4; nt++) {
            int col = n0 + wn * 32 + nt * 8 + (lane & 3) * 2;
            float bx = bias[col], by = bias[col + 1];
            if (row < M) {
                float2 v0 = make_float2(acc[mt][nt][0] + bx, acc[mt][nt][1] + by);
                *(float2*)(C + (size_t)row * ND + col) = v0;
            }
            if (row + 8 < M) {
                float2 v1 = make_float2(acc[mt][nt][2] + bx, acc[mt][nt][3] + by);
                *(float2*)(C + (size_t)(row + 8) * ND + col) = v1;
            }
        }
    }
}

// ---------------- BatchNorm stats + apply(+split) ----------------
__global__ void bn_stats_kernel(const float* __restrict__ pre, int n) {
    int f = threadIdx.x;
    float s = 0.f, sq = 0.f;
    for (int r = blockIdx.x; r < n; r += gridDim.x) {
        float v = pre[(size_t)r * HF + f];
        s += v; sq += v * v;
    }
    atomicAdd(&g_stats[f], s);
    atomicAdd(&g_stats[HF + f], sq);
}

// out fp32 = gelu(bn(pre)+res); also writes bf16 hi/lo split of out
__global__ void bn_apply_kernel(const float* __restrict__ pre, const float* __restrict__ res,
                                const float* __restrict__ gamma, const float* __restrict__ beta,
                                float* __restrict__ outp,
                                __nv_bfloat162* __restrict__ ohi, __nv_bfloat162* __restrict__ olo,
                                int n) {
    size_t i = (size_t)blockIdx.x * blockDim.x + threadIdx.x;
    size_t total4 = (size_t)n * HF / 4;
    if (i >= total4) return;
    int f = (int)((i * 4) % HF);
    float4 p  = ((const float4*)pre)[i];
    float4 sm = *(const float4*)&g_stats[f];
    float4 sq = *(const float4*)&g_stats[HF + f];
    float4 gm = *(const float4*)&gamma[f];
    float4 bt = *(const float4*)&beta[f];
    const float invn = 1.0f / (float)n;
    float4 o;
    {
        float mean = sm.x * invn, var = sq.x * invn - mean * mean;
        float v = gm.x * (p.x - mean) * rsqrtf(var + 1e-5f) + bt.x;
        if (res) v += ((const float4*)res)[i].x;
        o.x = gelu_exact(v);
    }
    {
        float mean = sm.y * invn, var = sq.y * invn - mean * mean;
        float v = gm.y * (p.y - mean) * rsqrtf(var + 1e-5f) + bt.y;
        if (res) v += ((const float4*)res)[i].y;
        o.y = gelu_exact(v);
    }
    {
        float mean = sm.z * invn, var = sq.z * invn - mean * mean;
        float v = gm.z * (p.z - mean) * rsqrtf(var + 1e-5f) + bt.z;
        if (res) v += ((const float4*)res)[i].z;
        o.z = gelu_exact(v);
    }
    {
        float mean = sm.w * invn, var = sq.w * invn - mean * mean;
        float v = gm.w * (p.w - mean) * rsqrtf(var + 1e-5f) + bt.w;
        if (res) v += ((const float4*)res)[i].w;
        o.w = gelu_exact(v);
    }
    ((float4*)outp)[i] = o;
    __nv_bfloat16 hx = __float2bfloat16(o.x), hy = __float2bfloat16(o.y);
    __nv_bfloat16 hz = __float2bfloat16(o.z), hw = __float2bfloat16(o.w);
    ohi[i * 2 + 0] = __nv_bfloat162(hx, hy);
    ohi[i * 2 + 1] = __nv_bfloat162(hz, hw);
    olo[i * 2 + 0] = __nv_bfloat162(__float2bfloat16(o.x - __bfloat162float(hx)),
                                    __float2bfloat16(o.y - __bfloat162float(hy)));
    olo[i * 2 + 1] = __nv_bfloat162(__float2bfloat16(o.z - __bfloat162float(hz)),
                                    __float2bfloat16(o.w - __bfloat162float(hw)));
}

// ---------------- propagation ----------------
__global__ void prop_init_kernel(float* __restrict__ acc, const float* __restrict__ alpha) {
    size_t i = (size_t)blockIdx.x * blockDim.x + threadIdx.x;
    if (i < (size_t)NN * OUTF) acc[i] = (alpha[0] * (1.0f / 1.5f)) * g_h[i];
}

__global__ __launch_bounds__(256)
void prop_kernel(const float* __restrict__ src, float* __restrict__ dst,
                 float* __restrict__ acc, const float* __restrict__ alpha, int k) {
    int r = blockIdx.x * 4 + (threadIdx.x >> 6);
    int t = threadIdx.x & 63;
    if (r >= NN) return;
    int s = g_rowptr[r], e = g_rowptr[r + 1];
    float a = 0.f;
    int i = s;
    for (; i + 4 <= e; i += 4) {
        int   c0 = g_cols[i + 0], c1 = g_cols[i + 1], c2 = g_cols[i + 2], c3 = g_cols[i + 3];
        float w0 = g_norm[i + 0], w1 = g_norm[i + 1], w2 = g_norm[i + 2], w3 = g_norm[i + 3];
        a += w0 * src[c0 * OUTF + t];
        a += w1 * src[c1 * OUTF + t];
        a += w2 * src[c2 * OUTF + t];
        a += w3 * src[c3 * OUTF + t];
    }
    for (; i < e; i++) a += g_norm[i] * src[g_cols[i] * OUTF + t];
    dst[(size_t)r * OUTF + t] = a;
    acc[(size_t)r * OUTF + t] += (alpha[k] * (1.0f / 1.5f)) * a;
}

// ---------------- launch ----------------
extern "C" void kernel_launch(void* const* d_in, const int* in_sizes, int n_in,
                              void* d_out, int out_size) {
    const float* x  = (const float*)d_in[0];
    const int*   ei = (const int*)d_in[1];
    const float *w1 = (const float*)d_in[2],  *b1 = (const float*)d_in[3];
    const float *ga1 = (const float*)d_in[4], *be1 = (const float*)d_in[5];
    const float *w2 = (const float*)d_in[6],  *b2 = (const float*)d_in[7];
    const float *ga2 = (const float*)d_in[8], *be2 = (const float*)d_in[9];
    const float *w3 = (const float*)d_in[10], *b3 = (const float*)d_in[11];
    const float *ga3 = (const float*)d_in[12], *be3 = (const float*)d_in[13];
    const float *w4 = (const float*)d_in[14], *b4 = (const float*)d_in[15];
    const float *alpha = (const float*)d_in[16];
    float* out = (float*)d_out;

    const int* rowp = ei;
    const int* colp = ei + EE;

    float *bufA, *bufB, *hbuf, *p1, *p2, *stats;
    __nv_bfloat16 *ahi, *alo, *w1h, *w1l, *w2h, *w2l, *w3h, *w3l, *w4h, *w4l;
    cudaGetSymbolAddress((void**)&bufA, g_bufA);
    cudaGetSymbolAddress((void**)&bufB, g_bufB);
    cudaGetSymbolAddress((void**)&hbuf, g_h);
    cudaGetSymbolAddress((void**)&p1, g_p1);
    cudaGetSymbolAddress((void**)&p2, g_p2);
    cudaGetSymbolAddress((void**)&stats, g_stats);
    cudaGetSymbolAddress((void**)&ahi, g_ahi);
    cudaGetSymbolAddress((void**)&alo, g_alo);
    cudaGetSymbolAddress((void**)&w1h, g_w1hi); cudaGetSymbolAddress((void**)&w1l, g_w1lo);
    cudaGetSymbolAddress((void**)&w2h, g_w2hi); cudaGetSymbolAddress((void**)&w2l, g_w2lo);
    cudaGetSymbolAddress((void**)&w3h, g_w3hi); cudaGetSymbolAddress((void**)&w3l, g_w3lo);
    cudaGetSymbolAddress((void**)&w4h, g_w4hi); cudaGetSymbolAddress((void**)&w4l, g_w4lo);

    // --- graph preprocessing ---
    init_kernel<<<(NN + 255) / 256, 256>>>();
    degree_kernel<<<(EE + 255) / 256, 256>>>(rowp);
    dinv_kernel<<<(NN + 255) / 256, 256>>>();
    const int nsb = (NN + 255) / 256;   // 391
    scan1_kernel<<<nsb, 256>>>();
    scan2_kernel<<<1, 512>>>(nsb);
    scan3_kernel<<<nsb, 256>>>();
    scatter_kernel<<<(TOTE + 255) / 256, 256>>>(rowp, colp);

    // --- operand conversions ---
    split2_kernel<<<(int)(((size_t)NN * INF / 2 + 255) / 256), 256>>>(
        x, (__nv_bfloat162*)ahi, (__nv_bfloat162*)alo, (size_t)NN * INF / 2);
    wsplit_kernel<<<(INF * HF + 255) / 256, 256>>>(w1, w1h, w1l, INF, HF);
    wsplit_kernel<<<(HF * HF + 255) / 256, 256>>>(w2, w2h, w2l, HF, HF);
    wsplit_kernel<<<(HF * HF + 255) / 256, 256>>>(w3, w3h, w3l, HF, HF);
    wsplit_kernel<<<(HF * OUTF + 255) / 256, 256>>>(w4, w4h, w4l, HF, OUTF);

    const int gx = (NN + 127) / 128;   // 782
    const int elem4 = (int)(((size_t)NN * HF / 4 + 255) / 256);

    // layer 1
    hmma_gemm_kernel<HF, INF><<<dim3(gx, HF / 64), 256>>>(ahi, alo, w1h, w1l, b1, bufA, NN);
    cudaMemsetAsync(stats, 0, 2 * HF * sizeof(float));
    bn_stats_kernel<<<1024, 256>>>(bufA, NN);
    bn_apply_kernel<<<elem4, 256>>>(bufA, nullptr, ga1, be1, bufB,
                                    (__nv_bfloat162*)ahi, (__nv_bfloat162*)alo, NN);
    // layer 2
    hmma_gemm_kernel<HF, HF><<<dim3(gx, HF / 64), 256>>>(ahi, alo, w2h, w2l, b2, bufA, NN);
    cudaMemsetAsync(stats, 0, 2 * HF * sizeof(float));
    bn_stats_kernel<<<1024, 256>>>(bufA, NN);
    bn_apply_kernel<<<elem4, 256>>>(bufA, bufB, ga2, be2, bufA,
                                    (__nv_bfloat162*)ahi, (__nv_bfloat162*)alo, NN);
    // layer 3
    hmma_gemm_kernel<HF, HF><<<dim3(gx, HF / 64), 256>>>(ahi, alo, w3h, w3l, b3, bufB, NN);
    cudaMemsetAsync(stats, 0, 2 * HF * sizeof(float));
    bn_stats_kernel<<<1024, 256>>>(bufB, NN);
    bn_apply_kernel<<<elem4, 256>>>(bufB, bufA, ga3, be3, bufB,
                                    (__nv_bfloat162*)ahi, (__nv_bfloat162*)alo, NN);
    // layer 4
    hmma_gemm_kernel<OUTF, HF><<<dim3(gx, 1), 256>>>(ahi, alo, w4h, w4l, b4, hbuf, NN);

    // --- propagation ---
    prop_init_kernel<<<(int)(((size_t)NN * OUTF + 255) / 256), 256>>>(out, alpha);
    const float* src = hbuf;
    float* dsts[2] = { p1, p2 };
    for (int k = 1; k <= 10; k++) {
        float* dst = dsts[(k - 1) & 1];
        prop_kernel<<<(NN + 3) / 4, 256>>>(src, dst, out, alpha, k);
        src = dst;
    }
}

// round 8
// speedup vs baseline: 1.7393x; 1.3710x over previous
#include <cuda_runtime.h>
#include <cuda_bf16.h>
#include <math.h>
#include <stdint.h>

// Problem constants
#define NN   100000
#define EE   3200000
#define INF  512
#define HF   256
#define OUTF 64
#define TOTE (EE + NN)

// ---------------- device scratch (no allocs allowed) ----------------
__device__ alignas(16) float g_bufA[(size_t)NN * HF];
__device__ alignas(16) float g_h  [(size_t)NN * OUTF];
__device__ alignas(16) float g_p1 [(size_t)NN * OUTF];
__device__ alignas(16) float g_p2 [(size_t)NN * OUTF];
__device__ float g_dinv[NN];
__device__ int   g_deg[NN];
__device__ int   g_cursor[NN];
__device__ int   g_rowptr[NN + 1];
__device__ alignas(16) int2 g_edge[TOTE];     // (col, norm-bits)
__device__ float g_stats[2 * HF];
__device__ int   g_bsum[512];
__device__ int   g_boff[512];

// bf16 split operand buffers (hi/lo), max shape 100k x 512
__device__ alignas(16) __nv_bfloat16 g_ahi[(size_t)NN * INF];
__device__ alignas(16) __nv_bfloat16 g_alo[(size_t)NN * INF];
// weight operands [Nd, K] (K-major)
__device__ alignas(16) __nv_bfloat16 g_w1hi[HF * INF],  g_w1lo[HF * INF];
__device__ alignas(16) __nv_bfloat16 g_w2hi[HF * HF],   g_w2lo[HF * HF];
__device__ alignas(16) __nv_bfloat16 g_w3hi[HF * HF],   g_w3lo[HF * HF];
__device__ alignas(16) __nv_bfloat16 g_w4hi[OUTF * HF], g_w4lo[OUTF * HF];

__device__ __forceinline__ float gelu_exact(float x) {
    return 0.5f * x * (1.0f + erff(x * 0.70710678118654752f));
}

__device__ __forceinline__ uint32_t smem_u32(const void* p) {
    uint32_t a;
    asm("{ .reg .u64 t; cvta.to.shared.u64 t, %1; cvt.u32.u64 %0, t; }" : "=r"(a) : "l"(p));
    return a;
}

#define LDSM_X4(r0, r1, r2, r3, addr) \
    asm volatile("ldmatrix.sync.aligned.m8n8.x4.shared.b16 {%0,%1,%2,%3}, [%4];" \
        : "=r"(r0), "=r"(r1), "=r"(r2), "=r"(r3) : "r"(addr))

#define MMA_BF16(c, a0, a1, a2, a3, b0, b1) \
    asm volatile("mma.sync.aligned.m16n8k16.row.col.f32.bf16.bf16.f32 " \
        "{%0,%1,%2,%3}, {%4,%5,%6,%7}, {%8,%9}, {%0,%1,%2,%3};" \
        : "+f"((c)[0]), "+f"((c)[1]), "+f"((c)[2]), "+f"((c)[3]) \
        : "r"(a0), "r"(a1), "r"(a2), "r"(a3), "r"(b0), "r"(b1))

__device__ __forceinline__ void cp16(uint32_t s, const void* g, bool p) {
    asm volatile("cp.async.ca.shared.global [%0], [%1], 16, %2;"
                 :: "r"(s), "l"(g), "r"(p ? 16 : 0));
}
#define CP_COMMIT() asm volatile("cp.async.commit_group;" ::: "memory")
#define CP_WAIT1()  asm volatile("cp.async.wait_group 1;" ::: "memory")

// ---------------- graph preprocessing ----------------
__global__ void init_kernel() {
    int i = blockIdx.x * blockDim.x + threadIdx.x;
    if (i < NN) { g_deg[i] = 1; g_cursor[i] = 0; }
}
__global__ void degree_kernel(const int* __restrict__ row) {
    int e = blockIdx.x * blockDim.x + threadIdx.x;
    if (e < EE) atomicAdd(&g_deg[row[e]], 1);
}
__global__ void dinv_kernel() {
    int i = blockIdx.x * blockDim.x + threadIdx.x;
    if (i < NN) g_dinv[i] = rsqrtf((float)g_deg[i]);
}
__global__ void scan1_kernel() {
    __shared__ int sh[256];
    int t = threadIdx.x, i = blockIdx.x * 256 + t;
    int v = (i < NN) ? g_deg[i] : 0;
    sh[t] = v; __syncthreads();
    for (int o = 1; o < 256; o <<= 1) {
        int u = (t >= o) ? sh[t - o] : 0;
        __syncthreads(); sh[t] += u; __syncthreads();
    }
    if (i < NN) g_rowptr[i] = sh[t] - v;
    if (t == 255) g_bsum[blockIdx.x] = sh[255];
}
__global__ void scan2_kernel(int nb) {
    __shared__ int sh[512];
    int t = threadIdx.x;
    int v = (t < nb) ? g_bsum[t] : 0;
    sh[t] = v; __syncthreads();
    for (int o = 1; o < 512; o <<= 1) {
        int u = (t >= o) ? sh[t - o] : 0;
        __syncthreads(); sh[t] += u; __syncthreads();
    }
    g_boff[t] = sh[t] - v;
}
__global__ void scan3_kernel() {
    int i = blockIdx.x * 256 + threadIdx.x;
    if (i < NN) g_rowptr[i] += g_boff[blockIdx.x];
    if (i == 0) g_rowptr[NN] = TOTE;
}
__global__ void scatter_kernel(const int* __restrict__ row, const int* __restrict__ col) {
    int idx = blockIdx.x * blockDim.x + threadIdx.x;
    if (idx >= TOTE) return;
    int r, c;
    if (idx < EE) { r = row[idx]; c = col[idx]; }
    else          { r = idx - EE; c = r; }
    int pos = g_rowptr[r] + atomicAdd(&g_cursor[r], 1);
    g_edge[pos] = make_int2(c, __float_as_int(g_dinv[r] * g_dinv[c]));
}

// ---------------- fp32 -> bf16 hi/lo splits ----------------
__global__ void split2_kernel(const float* __restrict__ in,
                              __nv_bfloat162* __restrict__ hi,
                              __nv_bfloat162* __restrict__ lo, size_t n2) {
    size_t i = (size_t)blockIdx.x * blockDim.x + threadIdx.x;
    if (i >= n2) return;
    float2 v = ((const float2*)in)[i];
    __nv_bfloat16 hx = __float2bfloat16(v.x), hy = __float2bfloat16(v.y);
    __nv_bfloat16 lx = __float2bfloat16(v.x - __bfloat162float(hx));
    __nv_bfloat16 ly = __float2bfloat16(v.y - __bfloat162float(hy));
    hi[i] = __nv_bfloat162(hx, hy);
    lo[i] = __nv_bfloat162(lx, ly);
}
__global__ void wsplit_kernel(const float* __restrict__ w,
                              __nv_bfloat16* __restrict__ whi,
                              __nv_bfloat16* __restrict__ wlo, int K, int Nd) {
    int idx = blockIdx.x * blockDim.x + threadIdx.x;
    if (idx >= K * Nd) return;
    int k = idx / Nd, n = idx % Nd;
    float v = w[(size_t)k * Nd + n];
    __nv_bfloat16 h = __float2bfloat16(v);
    whi[(size_t)n * K + k] = h;
    wlo[(size_t)n * K + k] = __float2bfloat16(v - __bfloat162float(h));
}

// ---------------- HMMA split-bf16 GEMM (cp.async 2-stage) ----------------
// C[M,ND] = A[M,KK]*B[ND,KK]^T + bias. 3-pass: AhBh + AhBl + AlBh.
// Block: 128 rows x 64 cols, BK=32, 8 warps (4M x 2N), warp tile 32x32.
// STATS: accumulate column sum/sumsq of C into g_stats (for BN).
// FUSEH: also write out[] = alpha[0]/1.5 * C (propagation init).
template <int ND, int KK, bool STATS, bool FUSEH>
__global__ __launch_bounds__(256)
void hmma_gemm_kernel(const __nv_bfloat16* __restrict__ Ahi, const __nv_bfloat16* __restrict__ Alo,
                      const __nv_bfloat16* __restrict__ Bhi, const __nv_bfloat16* __restrict__ Blo,
                      const float* __restrict__ bias, float* __restrict__ C, int M,
                      float* __restrict__ outp, const float* __restrict__ alpha) {
    constexpr int LDS = 40;                       // bf16 elems per smem row
    constexpr int AH_OFF = 0;
    constexpr int AL_OFF = 128 * LDS * 2;         // 10240
    constexpr int BH_OFF = AL_OFF + 128 * LDS * 2;// 20480
    constexpr int BL_OFF = BH_OFF + 64 * LDS * 2; // 25600
    constexpr int STAGE  = BL_OFF + 64 * LDS * 2; // 30720
    constexpr int NC = KK / 32;

    extern __shared__ __align__(16) char smem[];
    float* sSum = (float*)(smem + 2 * STAGE);
    float* sSq  = sSum + 64;

    const int tid = threadIdx.x, lane = tid & 31, warp = tid >> 5;
    const int wm = warp & 3, wn = warp >> 2;
    const int m0 = blockIdx.x * 128;
    const int n0 = blockIdx.y * 64;
    const uint32_t sb = smem_u32(smem);

    float acc[2][4][4];
#pragma unroll
    for (int i = 0; i < 2; i++)
#pragma unroll
        for (int j = 0; j < 4; j++)
#pragma unroll
            for (int q = 0; q < 4; q++) acc[i][j][q] = 0.f;

    const int ra = lane & 15;
    const int ca = (lane & 16) ? 8 : 0;
    const int rb = (lane & 7) + ((lane & 16) ? 8 : 0);
    const int cb = (lane & 8) ? 8 : 0;

    auto load_stage = [&](int c, int st) {
        if (c >= NC) return;
        const int k0 = c * 32;
        const uint32_t base = sb + st * STAGE;
#pragma unroll
        for (int it = tid; it < 512; it += 256) {
            int r = it >> 2, q = it & 3;
            int gr = m0 + r;
            bool p = gr < M;
            int grc = p ? gr : 0;
            uint32_t so = (uint32_t)(r * LDS + q * 8) * 2;
            cp16(base + AH_OFF + so, Ahi + (size_t)grc * KK + k0 + q * 8, p);
            cp16(base + AL_OFF + so, Alo + (size_t)grc * KK + k0 + q * 8, p);
        }
        {
            int r = tid >> 2, q = tid & 3;  // 64 rows x 4 chunks
            uint32_t so = (uint32_t)(r * LDS + q * 8) * 2;
            cp16(base + BH_OFF + so, Bhi + (size_t)(n0 + r) * KK + k0 + q * 8, true);
            cp16(base + BL_OFF + so, Blo + (size_t)(n0 + r) * KK + k0 + q * 8, true);
        }
    };

    load_stage(0, 0); CP_COMMIT();
    load_stage(1, 1); CP_COMMIT();

    for (int c = 0; c < NC; c++) {
        CP_WAIT1();
        __syncthreads();
        const int st = c & 1;
        const uint32_t base = sb + st * STAGE;
#pragma unroll
        for (int ks = 0; ks < 2; ks++) {
            const int kb = ks * 16;
            uint32_t ah[2][4], al[2][4], bh[2][4], bl[2][4];
#pragma unroll
            for (int mt = 0; mt < 2; mt++) {
                uint32_t off = (uint32_t)(((wm * 32 + mt * 16 + ra) * LDS + kb + ca) * 2);
                LDSM_X4(ah[mt][0], ah[mt][1], ah[mt][2], ah[mt][3], base + AH_OFF + off);
                LDSM_X4(al[mt][0], al[mt][1], al[mt][2], al[mt][3], base + AL_OFF + off);
            }
#pragma unroll
            for (int np = 0; np < 2; np++) {
                uint32_t off = (uint32_t)(((wn * 32 + np * 16 + rb) * LDS + kb + cb) * 2);
                LDSM_X4(bh[np][0], bh[np][1], bh[np][2], bh[np][3], base + BH_OFF + off);
                LDSM_X4(bl[np][0], bl[np][1], bl[np][2], bl[np][3], base + BL_OFF + off);
            }
#pragma unroll
            for (int mt = 0; mt < 2; mt++)
#pragma unroll
                for (int nt = 0; nt < 4; nt++) {
                    int np = nt >> 1, h = (nt & 1) * 2;
                    MMA_BF16(acc[mt][nt], ah[mt][0], ah[mt][1], ah[mt][2], ah[mt][3],
                             bh[np][h], bh[np][h + 1]);
                    MMA_BF16(acc[mt][nt], ah[mt][0], ah[mt][1], ah[mt][2], ah[mt][3],
                             bl[np][h], bl[np][h + 1]);
                    MMA_BF16(acc[mt][nt], al[mt][0], al[mt][1], al[mt][2], al[mt][3],
                             bh[np][h], bh[np][h + 1]);
                }
        }
        __syncthreads();
        load_stage(c + 2, st); CP_COMMIT();
    }

    // ---- epilogue ----
    if (STATS) {
        if (tid < 64) { sSum[tid] = 0.f; sSq[tid] = 0.f; }
        __syncthreads();
    }
    float a0 = 0.f;
    if (FUSEH) a0 = alpha[0] * (1.0f / 1.5f);

#pragma unroll
    for (int nt = 0; nt < 4; nt++) {
        float s0 = 0.f, s1 = 0.f, q0 = 0.f, q1 = 0.f;
        const int col = n0 + wn * 32 + nt * 8 + (lane & 3) * 2;
        const float bx = bias[col], by = bias[col + 1];
#pragma unroll
        for (int mt = 0; mt < 2; mt++) {
            int row = m0 + wm * 32 + mt * 16 + (lane >> 2);
            float v0 = acc[mt][nt][0] + bx, v1 = acc[mt][nt][1] + by;
            float v2 = acc[mt][nt][2] + bx, v3 = acc[mt][nt][3] + by;
            if (row < M) {
                *(float2*)(C + (size_t)row * ND + col) = make_float2(v0, v1);
                if (FUSEH) *(float2*)(outp + (size_t)row * ND + col) = make_float2(a0 * v0, a0 * v1);
                if (STATS) { s0 += v0; q0 += v0 * v0; s1 += v1; q1 += v1 * v1; }
            }
            if (row + 8 < M) {
                *(float2*)(C + (size_t)(row + 8) * ND + col) = make_float2(v2, v3);
                if (FUSEH) *(float2*)(outp + (size_t)(row + 8) * ND + col) = make_float2(a0 * v2, a0 * v3);
                if (STATS) { s0 += v2; q0 += v2 * v2; s1 += v3; q1 += v3 * v3; }
            }
        }
        if (STATS) {
#pragma unroll
            for (int m = 4; m < 32; m <<= 1) {
                s0 += __shfl_xor_sync(0xFFFFFFFFu, s0, m);
                s1 += __shfl_xor_sync(0xFFFFFFFFu, s1, m);
                q0 += __shfl_xor_sync(0xFFFFFFFFu, q0, m);
                q1 += __shfl_xor_sync(0xFFFFFFFFu, q1, m);
            }
            if (lane < 4) {
                int cl = wn * 32 + nt * 8 + lane * 2;
                atomicAdd(&sSum[cl], s0);     atomicAdd(&sSum[cl + 1], s1);
                atomicAdd(&sSq[cl], q0);      atomicAdd(&sSq[cl + 1], q1);
            }
        }
    }
    if (STATS) {
        __syncthreads();
        if (tid < 64) {
            atomicAdd(&g_stats[n0 + tid], sSum[tid]);
            atomicAdd(&g_stats[HF + n0 + tid], sSq[tid]);
        }
    }
}

// ---------------- BN apply + GELU + bf16 split (no fp32 output) ----------------
// v = bn(pre); if rhi: v += (rhi+rlo); o = gelu(v); write (ohi, olo).
__global__ void bn_apply_kernel(const float* __restrict__ pre,
                                const __nv_bfloat162* rhi, const __nv_bfloat162* rlo,
                                const float* __restrict__ gamma, const float* __restrict__ beta,
                                __nv_bfloat162* ohi, __nv_bfloat162* olo, int n) {
    size_t i = (size_t)blockIdx.x * blockDim.x + threadIdx.x;
    size_t total4 = (size_t)n * HF / 4;
    if (i >= total4) return;
    int f = (int)((i * 4) % HF);
    float4 p  = ((const float4*)pre)[i];
    float4 sm = *(const float4*)&g_stats[f];
    float4 sq = *(const float4*)&g_stats[HF + f];
    float4 gm = *(const float4*)&gamma[f];
    float4 bt = *(const float4*)&beta[f];
    const float invn = 1.0f / (float)n;
    float v0, v1, v2, v3;
    {
        float mean = sm.x * invn, var = sq.x * invn - mean * mean;
        v0 = gm.x * (p.x - mean) * rsqrtf(var + 1e-5f) + bt.x;
    }
    {
        float mean = sm.y * invn, var = sq.y * invn - mean * mean;
        v1 = gm.y * (p.y - mean) * rsqrtf(var + 1e-5f) + bt.y;
    }
    {
        float mean = sm.z * invn, var = sq.z * invn - mean * mean;
        v2 = gm.z * (p.z - mean) * rsqrtf(var + 1e-5f) + bt.z;
    }
    {
        float mean = sm.w * invn, var = sq.w * invn - mean * mean;
        v3 = gm.w * (p.w - mean) * rsqrtf(var + 1e-5f) + bt.w;
    }
    if (rhi) {
        __nv_bfloat162 h0 = rhi[i * 2], h1 = rhi[i * 2 + 1];
        __nv_bfloat162 l0 = rlo[i * 2], l1 = rlo[i * 2 + 1];
        v0 += __bfloat162float(h0.x) + __bfloat162float(l0.x);
        v1 += __bfloat162float(h0.y) + __bfloat162float(l0.y);
        v2 += __bfloat162float(h1.x) + __bfloat162float(l1.x);
        v3 += __bfloat162float(h1.y) + __bfloat162float(l1.y);
    }
    float o0 = gelu_exact(v0), o1 = gelu_exact(v1);
    float o2 = gelu_exact(v2), o3 = gelu_exact(v3);
    __nv_bfloat16 h0 = __float2bfloat16(o0), h1 = __float2bfloat16(o1);
    __nv_bfloat16 h2 = __float2bfloat16(o2), h3 = __float2bfloat16(o3);
    ohi[i * 2 + 0] = __nv_bfloat162(h0, h1);
    ohi[i * 2 + 1] = __nv_bfloat162(h2, h3);
    olo[i * 2 + 0] = __nv_bfloat162(__float2bfloat16(o0 - __bfloat162float(h0)),
                                    __float2bfloat16(o1 - __bfloat162float(h1)));
    olo[i * 2 + 1] = __nv_bfloat162(__float2bfloat16(o2 - __bfloat162float(h2)),
                                    __float2bfloat16(o3 - __bfloat162float(h3)));
}

// ---------------- propagation: 1 warp/row, float2 per lane ----------------
__global__ __launch_bounds__(256)
void prop_kernel(const float2* __restrict__ src, float2* __restrict__ dst,
                 float2* __restrict__ acc, const float* __restrict__ alpha, int k) {
    int r = (blockIdx.x * 256 + threadIdx.x) >> 5;
    int lane = threadIdx.x & 31;
    if (r >= NN) return;
    int s = g_rowptr[r], e = g_rowptr[r + 1];
    float ax = 0.f, ay = 0.f;
    int i = s;
    for (; i + 4 <= e; i += 4) {
        int2 e0 = g_edge[i], e1 = g_edge[i + 1], e2 = g_edge[i + 2], e3 = g_edge[i + 3];
        float2 v0 = src[(size_t)e0.x * 32 + lane];
        float2 v1 = src[(size_t)e1.x * 32 + lane];
        float2 v2 = src[(size_t)e2.x * 32 + lane];
        float2 v3 = src[(size_t)e3.x * 32 + lane];
        float w0 = __int_as_float(e0.y), w1 = __int_as_float(e1.y);
        float w2 = __int_as_float(e2.y), w3 = __int_as_float(e3.y);
        ax += w0 * v0.x; ay += w0 * v0.y;
        ax += w1 * v1.x; ay += w1 * v1.y;
        ax += w2 * v2.x; ay += w2 * v2.y;
        ax += w3 * v3.x; ay += w3 * v3.y;
    }
    for (; i < e; i++) {
        int2 ed = g_edge[i];
        float2 v = src[(size_t)ed.x * 32 + lane];
        float w = __int_as_float(ed.y);
        ax += w * v.x; ay += w * v.y;
    }
    size_t o = (size_t)r * 32 + lane;
    dst[o] = make_float2(ax, ay);
    float aa = alpha[k] * (1.0f / 1.5f);
    float2 ac = acc[o];
    ac.x += aa * ax; ac.y += aa * ay;
    acc[o] = ac;
}

// ---------------- launch ----------------
extern "C" void kernel_launch(void* const* d_in, const int* in_sizes, int n_in,
                              void* d_out, int out_size) {
    const float* x  = (const float*)d_in[0];
    const int*   ei = (const int*)d_in[1];
    const float *w1 = (const float*)d_in[2],  *b1 = (const float*)d_in[3];
    const float *ga1 = (const float*)d_in[4], *be1 = (const float*)d_in[5];
    const float *w2 = (const float*)d_in[6],  *b2 = (const float*)d_in[7];
    const float *ga2 = (const float*)d_in[8], *be2 = (const float*)d_in[9];
    const float *w3 = (const float*)d_in[10], *b3 = (const float*)d_in[11];
    const float *ga3 = (const float*)d_in[12], *be3 = (const float*)d_in[13];
    const float *w4 = (const float*)d_in[14], *b4 = (const float*)d_in[15];
    const float *alpha = (const float*)d_in[16];
    float* out = (float*)d_out;

    const int* rowp = ei;
    const int* colp = ei + EE;

    float *bufA, *hbuf, *p1, *p2, *stats;
    __nv_bfloat16 *ahi, *alo, *w1h, *w1l, *w2h, *w2l, *w3h, *w3l, *w4h, *w4l;
    cudaGetSymbolAddress((void**)&bufA, g_bufA);
    cudaGetSymbolAddress((void**)&hbuf, g_h);
    cudaGetSymbolAddress((void**)&p1, g_p1);
    cudaGetSymbolAddress((void**)&p2, g_p2);
    cudaGetSymbolAddress((void**)&stats, g_stats);
    cudaGetSymbolAddress((void**)&ahi, g_ahi);
    cudaGetSymbolAddress((void**)&alo, g_alo);
    cudaGetSymbolAddress((void**)&w1h, g_w1hi); cudaGetSymbolAddress((void**)&w1l, g_w1lo);
    cudaGetSymbolAddress((void**)&w2h, g_w2hi); cudaGetSymbolAddress((void**)&w2l, g_w2lo);
    cudaGetSymbolAddress((void**)&w3h, g_w3hi); cudaGetSymbolAddress((void**)&w3l, g_w3lo);
    cudaGetSymbolAddress((void**)&w4h, g_w4hi); cudaGetSymbolAddress((void**)&w4l, g_w4lo);

    const int SMEM = 2 * 30720 + 2 * 64 * (int)sizeof(float);
    cudaFuncSetAttribute(hmma_gemm_kernel<HF, INF, true, false>,
                         cudaFuncAttributeMaxDynamicSharedMemorySize, SMEM);
    cudaFuncSetAttribute(hmma_gemm_kernel<HF, HF, true, false>,
                         cudaFuncAttributeMaxDynamicSharedMemorySize, SMEM);
    cudaFuncSetAttribute(hmma_gemm_kernel<OUTF, HF, false, true>,
                         cudaFuncAttributeMaxDynamicSharedMemorySize, SMEM);

    // --- graph preprocessing ---
    init_kernel<<<(NN + 255) / 256, 256>>>();
    degree_kernel<<<(EE + 255) / 256, 256>>>(rowp);
    dinv_kernel<<<(NN + 255) / 256, 256>>>();
    const int nsb = (NN + 255) / 256;
    scan1_kernel<<<nsb, 256>>>();
    scan2_kernel<<<1, 512>>>(nsb);
    scan3_kernel<<<nsb, 256>>>();
    scatter_kernel<<<(TOTE + 255) / 256, 256>>>(rowp, colp);

    // --- operand conversions ---
    split2_kernel<<<(int)(((size_t)NN * INF / 2 + 255) / 256), 256>>>(
        x, (__nv_bfloat162*)ahi, (__nv_bfloat162*)alo, (size_t)NN * INF / 2);
    wsplit_kernel<<<(INF * HF + 255) / 256, 256>>>(w1, w1h, w1l, INF, HF);
    wsplit_kernel<<<(HF * HF + 255) / 256, 256>>>(w2, w2h, w2l, HF, HF);
    wsplit_kernel<<<(HF * HF + 255) / 256, 256>>>(w3, w3h, w3l, HF, HF);
    wsplit_kernel<<<(HF * OUTF + 255) / 256, 256>>>(w4, w4h, w4l, HF, OUTF);

    const int gx = (NN + 127) / 128;   // 782
    const int elem4 = (int)(((size_t)NN * HF / 4 + 255) / 256);

    // layer 1
    cudaMemsetAsync(stats, 0, 2 * HF * sizeof(float));
    hmma_gemm_kernel<HF, INF, true, false><<<dim3(gx, HF / 64), 256, SMEM>>>(
        ahi, alo, w1h, w1l, b1, bufA, NN, nullptr, nullptr);
    bn_apply_kernel<<<elem4, 256>>>(bufA, nullptr, nullptr, ga1, be1,
                                    (__nv_bfloat162*)ahi, (__nv_bfloat162*)alo, NN);
    // layer 2
    cudaMemsetAsync(stats, 0, 2 * HF * sizeof(float));
    hmma_gemm_kernel<HF, HF, true, false><<<dim3(gx, HF / 64), 256, SMEM>>>(
        ahi, alo, w2h, w2l, b2, bufA, NN, nullptr, nullptr);
    bn_apply_kernel<<<elem4, 256>>>(bufA, (__nv_bfloat162*)ahi, (__nv_bfloat162*)alo, ga2, be2,
                                    (__nv_bfloat162*)ahi, (__nv_bfloat162*)alo, NN);
    // layer 3
    cudaMemsetAsync(stats, 0, 2 * HF * sizeof(float));
    hmma_gemm_kernel<HF, HF, true, false><<<dim3(gx, HF / 64), 256, SMEM>>>(
        ahi, alo, w3h, w3l, b3, bufA, NN, nullptr, nullptr);
    bn_apply_kernel<<<elem4, 256>>>(bufA, (__nv_bfloat162*)ahi, (__nv_bfloat162*)alo, ga3, be3,
                                    (__nv_bfloat162*)ahi, (__nv_bfloat162*)alo, NN);
    // layer 4 (+ fused prop-init: out = alpha0/1.5 * h)
    hmma_gemm_kernel<OUTF, HF, false, true><<<dim3(gx, 1), 256, SMEM>>>(
        ahi, alo, w4h, w4l, b4, hbuf, NN, out, alpha);

    // --- propagation ---
    const float* src = hbuf;
    float* dsts[2] = { p1, p2 };
    for (int k = 1; k <= 10; k++) {
        float* dst = dsts[(k - 1) & 1];
        prop_kernel<<<(NN * 32 + 255) / 256, 256>>>(
            (const float2*)src, (float2*)dst, (float2*)out, alpha, k);
        src = dst;
    }
}